// round 1
// baseline (speedup 1.0000x reference)
#include <cuda_runtime.h>

// BilinearInterpolation: projective warp + bilinear sample.
// X: (16, 384, 384, 64) fp32 ; T: (16, 9) fp32 ; out: (16, 224, 224, 64) fp32.
//
// One thread = one (batch, out-pixel, 4-channel float4 group).
// 16 threads per pixel -> 4 coalesced float4 corner gathers + 1 float4 store.

#define OUT_H 224
#define OUT_W 224
#define HIN   384
#define WIN   384
#define CVEC  16   // 64 channels / 4 per float4

__global__ __launch_bounds__(256)
void bilerp_kernel(const float* __restrict__ X,
                   const float* __restrict__ T,
                   float* __restrict__ out,
                   int total)
{
    int tid = blockIdx.x * blockDim.x + threadIdx.x;
    if (tid >= total) return;

    const int N = OUT_H * OUT_W;
    int g   = tid & (CVEC - 1);   // channel group within pixel
    int p   = tid >> 4;           // (b, pixel) flat index
    int b   = p / N;
    int pix = p - b * N;
    int oy  = pix / OUT_W;
    int ox  = pix - oy * OUT_W;

    // grid point in [-1,1]^2 (linspace with endpoints: step = 2/(W-1))
    float gx = -1.0f + (float)ox * (2.0f / (float)(OUT_W - 1));
    float gy = -1.0f + (float)oy * (2.0f / (float)(OUT_H - 1));

    const float* Tb = T + b * 9;
    float t0 = __ldg(Tb + 0), t1 = __ldg(Tb + 1), t2 = __ldg(Tb + 2);
    float t3 = __ldg(Tb + 3), t4 = __ldg(Tb + 4), t5 = __ldg(Tb + 5);
    float t6 = __ldg(Tb + 6), t7 = __ldg(Tb + 7), t8 = __ldg(Tb + 8);

    float sx = t0 * gx + t1 * gy + t2;
    float sy = t3 * gx + t4 * gy + t5;
    float sz = t6 * gx + t7 * gy + t8 + 1e-6f;

    float x = 0.5f * (sx / sz + 1.0f) * (float)WIN;
    float y = 0.5f * (sy / sz + 1.0f) * (float)HIN;

    // truncation toward zero (matches astype(int32) / tf.cast)
    int x0 = (int)x;
    int y0 = (int)y;
    int x1 = x0 + 1;
    int y1 = y0 + 1;
    x0 = min(max(x0, 0), WIN - 1);
    x1 = min(max(x1, 0), WIN - 1);
    y0 = min(max(y0, 0), HIN - 1);
    y1 = min(max(y1, 0), HIN - 1);

    float x0f = (float)x0, x1f = (float)x1;
    float y0f = (float)y0, y1f = (float)y1;

    float wa = (x1f - x) * (y1f - y);
    float wb = (x1f - x) * (y - y0f);
    float wc = (x - x0f) * (y1f - y);
    float wd = (x - x0f) * (y - y0f);

    const float4* Xv = (const float4*)X;
    size_t bbase = (size_t)b * HIN * WIN * CVEC;
    size_t r0 = bbase + (size_t)y0 * (WIN * CVEC);
    size_t r1 = bbase + (size_t)y1 * (WIN * CVEC);

    float4 pa = __ldg(Xv + r0 + (size_t)x0 * CVEC + g);
    float4 pb = __ldg(Xv + r1 + (size_t)x0 * CVEC + g);
    float4 pc = __ldg(Xv + r0 + (size_t)x1 * CVEC + g);
    float4 pd = __ldg(Xv + r1 + (size_t)x1 * CVEC + g);

    float4 o;
    o.x = wa * pa.x + wb * pb.x + wc * pc.x + wd * pd.x;
    o.y = wa * pa.y + wb * pb.y + wc * pc.y + wd * pd.y;
    o.z = wa * pa.z + wb * pb.z + wc * pc.z + wd * pd.z;
    o.w = wa * pa.w + wb * pb.w + wc * pc.w + wd * pd.w;

    ((float4*)out)[(size_t)p * CVEC + g] = o;
}

extern "C" void kernel_launch(void* const* d_in, const int* in_sizes, int n_in,
                              void* d_out, int out_size)
{
    const float* X = (const float*)d_in[0];
    const float* T = (const float*)d_in[1];
    float* out = (float*)d_out;

    const int total = 16 * OUT_H * OUT_W * CVEC;  // 12,845,056 threads
    const int threads = 256;
    const int blocks = (total + threads - 1) / threads;
    bilerp_kernel<<<blocks, threads>>>(X, T, out, total);
}

// round 2
// speedup vs baseline: 1.0078x; 1.0078x over previous
#include <cuda_runtime.h>

// BilinearInterpolation: projective warp + bilinear sample.
// X: (16, 384, 384, 64) fp32 ; T: (16, 9) fp32 ; out: (16, 224, 224, 64) fp32.
//
// One thread = one (batch, out-pixel, TWO 4-channel float4 groups g and g+8).
// 8 threads per pixel -> 8 coalesced float4 corner gathers + 2 float4 streaming
// stores per thread. Doubles memory-level parallelism vs the R1 kernel and
// halves the redundant per-pixel transform math.

#define OUT_H 224
#define OUT_W 224
#define HIN   384
#define WIN   384
#define CVEC  16   // 64 channels / 4 per float4

__global__ __launch_bounds__(256)
void bilerp_kernel(const float* __restrict__ X,
                   const float* __restrict__ T,
                   float* __restrict__ out,
                   int total)
{
    int tid = blockIdx.x * blockDim.x + threadIdx.x;
    if (tid >= total) return;

    const int N = OUT_H * OUT_W;
    int g   = tid & 7;            // channel group within pixel (0..7)
    int p   = tid >> 3;           // (b, pixel) flat index
    int b   = p / N;
    int pix = p - b * N;
    int oy  = pix / OUT_W;
    int ox  = pix - oy * OUT_W;

    // grid point in [-1,1]^2 (linspace with endpoints: step = 2/(W-1))
    float gx = -1.0f + (float)ox * (2.0f / (float)(OUT_W - 1));
    float gy = -1.0f + (float)oy * (2.0f / (float)(OUT_H - 1));

    const float* Tb = T + b * 9;
    float t0 = __ldg(Tb + 0), t1 = __ldg(Tb + 1), t2 = __ldg(Tb + 2);
    float t3 = __ldg(Tb + 3), t4 = __ldg(Tb + 4), t5 = __ldg(Tb + 5);
    float t6 = __ldg(Tb + 6), t7 = __ldg(Tb + 7), t8 = __ldg(Tb + 8);

    float sx = t0 * gx + t1 * gy + t2;
    float sy = t3 * gx + t4 * gy + t5;
    float sz = t6 * gx + t7 * gy + t8 + 1e-6f;

    float rz = 1.0f / sz;
    float x = 0.5f * (sx * rz + 1.0f) * (float)WIN;
    float y = 0.5f * (sy * rz + 1.0f) * (float)HIN;

    // truncation toward zero (matches astype(int32) / tf.cast)
    int x0 = (int)x;
    int y0 = (int)y;
    int x1 = x0 + 1;
    int y1 = y0 + 1;
    x0 = min(max(x0, 0), WIN - 1);
    x1 = min(max(x1, 0), WIN - 1);
    y0 = min(max(y0, 0), HIN - 1);
    y1 = min(max(y1, 0), HIN - 1);

    float x0f = (float)x0, x1f = (float)x1;
    float y0f = (float)y0, y1f = (float)y1;

    float wa = (x1f - x) * (y1f - y);
    float wb = (x1f - x) * (y - y0f);
    float wc = (x - x0f) * (y1f - y);
    float wd = (x - x0f) * (y - y0f);

    const float4* Xv = (const float4*)X;
    size_t bbase = (size_t)b * HIN * WIN * CVEC;
    size_t r0 = bbase + (size_t)y0 * (WIN * CVEC);
    size_t r1 = bbase + (size_t)y1 * (WIN * CVEC);
    size_t ca = (size_t)x0 * CVEC + g;   // corner column offsets
    size_t cc = (size_t)x1 * CVEC + g;

    // 8 independent 16B loads in flight (two channel groups: g, g+8)
    float4 pa0 = __ldg(Xv + r0 + ca);
    float4 pb0 = __ldg(Xv + r1 + ca);
    float4 pc0 = __ldg(Xv + r0 + cc);
    float4 pd0 = __ldg(Xv + r1 + cc);
    float4 pa1 = __ldg(Xv + r0 + ca + 8);
    float4 pb1 = __ldg(Xv + r1 + ca + 8);
    float4 pc1 = __ldg(Xv + r0 + cc + 8);
    float4 pd1 = __ldg(Xv + r1 + cc + 8);

    float4 o0, o1;
    o0.x = wa * pa0.x + wb * pb0.x + wc * pc0.x + wd * pd0.x;
    o0.y = wa * pa0.y + wb * pb0.y + wc * pc0.y + wd * pd0.y;
    o0.z = wa * pa0.z + wb * pb0.z + wc * pc0.z + wd * pd0.z;
    o0.w = wa * pa0.w + wb * pb0.w + wc * pc0.w + wd * pd0.w;
    o1.x = wa * pa1.x + wb * pb1.x + wc * pc1.x + wd * pd1.x;
    o1.y = wa * pa1.y + wb * pb1.y + wc * pc1.y + wd * pd1.y;
    o1.z = wa * pa1.z + wb * pb1.z + wc * pc1.z + wd * pd1.z;
    o1.w = wa * pa1.w + wb * pb1.w + wc * pc1.w + wd * pd1.w;

    // streaming stores: write-once output, keep it out of L2's way
    float4* ob = (float4*)out + (size_t)p * CVEC + g;
    __stcs(ob,     o0);
    __stcs(ob + 8, o1);
}

extern "C" void kernel_launch(void* const* d_in, const int* in_sizes, int n_in,
                              void* d_out, int out_size)
{
    const float* X = (const float*)d_in[0];
    const float* T = (const float*)d_in[1];
    float* out = (float*)d_out;

    const int total = 16 * OUT_H * OUT_W * 8;  // 6,422,528 threads
    const int threads = 256;
    const int blocks = (total + threads - 1) / threads;
    bilerp_kernel<<<blocks, threads>>>(X, T, out, total);
}